// round 1
// baseline (speedup 1.0000x reference)
#include <cuda_runtime.h>

// ---------------- scratch (no allocation allowed) ----------------
#define NMAXN 50048
#define GMAX  2048

__device__ float g_bufA[NMAXN * 128];
__device__ float g_bufB[NMAXN * 128];
__device__ float g_deg[NMAXN];
__device__ float g_dinv[NMAXN];
__device__ float g_invdeg[NMAXN];
__device__ float g_stats[256];          // [sum(0..M), sumsq(M..2M)]
__device__ float g_pc[GMAX * 64];
__device__ float g_ps[GMAX * 64];
__device__ float g_cnt[GMAX];
__device__ float g_hcat[GMAX * 128];
__device__ float g_headT[GMAX * 64];

// ---------------- kernels ----------------
__global__ void k_zero(float* p, int n) {
    int i = blockIdx.x * blockDim.x + threadIdx.x;
    if (i < n) p[i] = 0.f;
}

__global__ void k_count(const int* __restrict__ idx, int n, float* __restrict__ acc) {
    int i = blockIdx.x * blockDim.x + threadIdx.x;
    if (i < n) atomicAdd(&acc[idx[i]], 1.f);
}

__global__ void k_degfin(const float* __restrict__ deg, float* __restrict__ dinv,
                         float* __restrict__ invdeg, int N) {
    int i = blockIdx.x * blockDim.x + threadIdx.x;
    if (i < N) {
        float d = deg[i] + 1.f;
        dinv[i] = rsqrtf(d);
        invdeg[i] = 1.f / d;
    }
}

// X[N,K] @ W[K,M] (+bias) -> H[N,M].  blockDim = M, R rows per block.
template <int K, int M, int R>
__global__ void k_gemm(const float* __restrict__ X, const float* __restrict__ W,
                       const float* __restrict__ bias, float* __restrict__ H, int N) {
    __shared__ float xs[R * K];
    int row0 = blockIdx.x * R;
    for (int i = threadIdx.x; i < R * K; i += M) {
        int r = i / K, k = i - r * K;
        int row = row0 + r;
        xs[i] = (row < N) ? X[(size_t)row * K + k] : 0.f;
    }
    __syncthreads();
    int col = threadIdx.x;
    float b = bias ? bias[col] : 0.f;
    float acc[R];
#pragma unroll
    for (int r = 0; r < R; r++) acc[r] = b;
    for (int k = 0; k < K; k++) {
        float w = W[k * M + col];
#pragma unroll
        for (int r = 0; r < R; r++) acc[r] += xs[r * K + k] * w;
    }
#pragma unroll
    for (int r = 0; r < R; r++) {
        int row = row0 + r;
        if (row < N) H[(size_t)row * M + col] = acc[r];
    }
}

// A = H * invdeg[row] + bias[col]   (self-loop term initializes the accumulator)
__global__ void k_selfinit(const float* __restrict__ H, const float* __restrict__ invdeg,
                           const float* __restrict__ bias, float* __restrict__ A,
                           int N, int M) {
    int idx = blockIdx.x * blockDim.x + threadIdx.x;
    if (idx < N * M) {
        int i = idx / M, c = idx - i * M;
        A[idx] = H[idx] * invdeg[i] + bias[c];
    }
}

// per (edge, float4) atomic scatter: A[dst] += H[src] * dinv[src]*dinv[dst]
template <int M>
__global__ void k_agg(const int* __restrict__ src, const int* __restrict__ dst,
                      const float* __restrict__ dinv, const float* __restrict__ H,
                      float* __restrict__ A, int E) {
    const int Q = M / 4;
    int idx = blockIdx.x * blockDim.x + threadIdx.x;
    int e = idx / Q, q = idx - e * Q;
    if (e >= E) return;
    int s = src[e], d = dst[e];
    float nrm = dinv[s] * dinv[d];
    float4 h = *(const float4*)(H + (size_t)s * M + q * 4);
    float* out = A + (size_t)d * M + q * 4;
    atomicAdd(out + 0, h.x * nrm);
    atomicAdd(out + 1, h.y * nrm);
    atomicAdd(out + 2, h.z * nrm);
    atomicAdd(out + 3, h.w * nrm);
}

// column sums / sums of squares, blockDim = M, 64 rows per block
__global__ void k_bnstats(const float* __restrict__ A, float* __restrict__ stats,
                          int N, int M) {
    int c = threadIdx.x;
    int row0 = blockIdx.x * 64;
    int rend = min(row0 + 64, N);
    float s = 0.f, sq = 0.f;
    for (int r = row0; r < rend; r++) {
        float v = A[(size_t)r * M + c];
        s += v;
        sq += v * v;
    }
    atomicAdd(&stats[c], s);
    atomicAdd(&stats[M + c], sq);
}

__global__ void k_bnrelu(const float* __restrict__ A, const float* __restrict__ stats,
                         const float* __restrict__ gamma, const float* __restrict__ beta,
                         float* __restrict__ out, int N, int M) {
    int idx = blockIdx.x * blockDim.x + threadIdx.x;
    if (idx < N * M) {
        int c = idx % M;
        float inv_n = 1.f / (float)N;
        float mean = stats[c] * inv_n;
        float var = stats[M + c] * inv_n - mean * mean;
        float v = (A[idx] - mean) * rsqrtf(var + 1e-5f) * gamma[c] + beta[c];
        out[idx] = fmaxf(v, 0.f);
    }
}

__global__ void k_pool(const float* __restrict__ act, const int* __restrict__ batch,
                       float* __restrict__ pooled, int N) {
    int idx = blockIdx.x * blockDim.x + threadIdx.x;
    if (idx < N * 64) {
        int i = idx >> 6, c = idx & 63;
        atomicAdd(&pooled[batch[i] * 64 + c], act[idx]);
    }
}

__global__ void k_hcat(const float* __restrict__ pc, const float* __restrict__ ps,
                       const float* __restrict__ cnt, float* __restrict__ hcat, int G) {
    int idx = blockIdx.x * blockDim.x + threadIdx.x;
    if (idx < G * 128) {
        int g = idx >> 7, c = idx & 127;
        float inv = 1.f / fmaxf(cnt[g], 1.f);
        hcat[idx] = ((c < 64) ? pc[g * 64 + c] : ps[g * 64 + (c - 64)]) * inv;
    }
}

__global__ void k_headout(const float* __restrict__ T, const float* __restrict__ stats,
                          const float* __restrict__ gamma, const float* __restrict__ beta,
                          const float* __restrict__ Wf2, const float* __restrict__ bf2,
                          float* __restrict__ out, int G) {
    int g = blockIdx.x * blockDim.x + threadIdx.x;
    if (g >= G) return;
    float inv_g = 1.f / (float)G;
    float acc = bf2[0];
    for (int j = 0; j < 64; j++) {
        float mean = stats[j] * inv_g;
        float var = stats[64 + j] * inv_g - mean * mean;
        float v = (T[g * 64 + j] - mean) * rsqrtf(var + 1e-5f) * gamma[j] + beta[j];
        acc += fmaxf(v, 0.f) * Wf2[j];
    }
    out[g] = acc;
}

// ---------------- host ----------------
static inline int ceil_div(int a, int b) { return (a + b - 1) / b; }

extern "C" void kernel_launch(void* const* d_in, const int* in_sizes, int n_in,
                              void* d_out, int out_size) {
    const float* xc   = (const float*)d_in[0];
    const float* xs_  = (const float*)d_in[1];
    const int*   eic  = (const int*)d_in[2];
    const int*   eis  = (const int*)d_in[3];
    const int*   batch= (const int*)d_in[4];
    const float* W1c = (const float*)d_in[5],  *b1c = (const float*)d_in[6];
    const float* g1c = (const float*)d_in[7],  *be1c= (const float*)d_in[8];
    const float* W2c = (const float*)d_in[9],  *b2c = (const float*)d_in[10];
    const float* g2c = (const float*)d_in[11], *be2c= (const float*)d_in[12];
    const float* W1s = (const float*)d_in[13], *b1s = (const float*)d_in[14];
    const float* g1s = (const float*)d_in[15], *be1s= (const float*)d_in[16];
    const float* W2s = (const float*)d_in[17], *b2s = (const float*)d_in[18];
    const float* g2s = (const float*)d_in[19], *be2s= (const float*)d_in[20];
    const float* Wf1 = (const float*)d_in[21], *bf1 = (const float*)d_in[22];
    const float* gf1 = (const float*)d_in[23], *bef1= (const float*)d_in[24];
    const float* Wf2 = (const float*)d_in[25], *bf2 = (const float*)d_in[26];

    const int N = in_sizes[0] / 64;
    const int E = in_sizes[2] / 2;
    const int G = out_size;            // OUT_DIM = 1

    float *bufA, *bufB, *deg, *dinv, *invdeg, *stats, *pc, *ps, *cnt, *hcat, *headT;
    cudaGetSymbolAddress((void**)&bufA, g_bufA);
    cudaGetSymbolAddress((void**)&bufB, g_bufB);
    cudaGetSymbolAddress((void**)&deg, g_deg);
    cudaGetSymbolAddress((void**)&dinv, g_dinv);
    cudaGetSymbolAddress((void**)&invdeg, g_invdeg);
    cudaGetSymbolAddress((void**)&stats, g_stats);
    cudaGetSymbolAddress((void**)&pc, g_pc);
    cudaGetSymbolAddress((void**)&ps, g_ps);
    cudaGetSymbolAddress((void**)&cnt, g_cnt);
    cudaGetSymbolAddress((void**)&hcat, g_hcat);
    cudaGetSymbolAddress((void**)&headT, g_headT);

    // pooled accumulators + graph counts (shared across branches)
    k_zero<<<ceil_div(G * 64, 256), 256>>>(pc, G * 64);
    k_zero<<<ceil_div(G * 64, 256), 256>>>(ps, G * 64);
    k_zero<<<ceil_div(G, 256), 256>>>(cnt, G);
    k_count<<<ceil_div(N, 256), 256>>>(batch, N, cnt);

    auto run_branch = [&](const float* x, const int* ei,
                          const float* W1, const float* b1, const float* ga1, const float* bt1,
                          const float* W2, const float* b2, const float* ga2, const float* bt2,
                          float* pooled) {
        const int* src = ei;
        const int* dst = ei + E;
        // degree / normalization
        k_zero<<<ceil_div(N, 256), 256>>>(deg, N);
        k_count<<<ceil_div(E, 256), 256>>>(dst, E, deg);
        k_degfin<<<ceil_div(N, 256), 256>>>(deg, dinv, invdeg, N);

        // ---- layer 1: 64 -> 128 ----
        k_gemm<64, 128, 8><<<ceil_div(N, 8), 128>>>(x, W1, nullptr, bufB, N);
        k_selfinit<<<ceil_div(N * 128, 256), 256>>>(bufB, invdeg, b1, bufA, N, 128);
        k_agg<128><<<ceil_div(E * 32, 256), 256>>>(src, dst, dinv, bufB, bufA, E);
        k_zero<<<1, 256>>>(stats, 256);
        k_bnstats<<<ceil_div(N, 64), 128>>>(bufA, stats, N, 128);
        k_bnrelu<<<ceil_div(N * 128, 256), 256>>>(bufA, stats, ga1, bt1, bufB, N, 128);

        // ---- layer 2: 128 -> 64 ----
        k_gemm<128, 64, 8><<<ceil_div(N, 8), 64>>>(bufB, W2, nullptr, bufA, N);
        k_selfinit<<<ceil_div(N * 64, 256), 256>>>(bufA, invdeg, b2, bufB, N, 64);
        k_agg<64><<<ceil_div(E * 16, 256), 256>>>(src, dst, dinv, bufA, bufB, E);
        k_zero<<<1, 128>>>(stats, 128);
        k_bnstats<<<ceil_div(N, 64), 64>>>(bufB, stats, N, 64);
        k_bnrelu<<<ceil_div(N * 64, 256), 256>>>(bufB, stats, ga2, bt2, bufA, N, 64);

        // ---- mean pool (sum; divide later in hcat) ----
        k_pool<<<ceil_div(N * 64, 256), 256>>>(bufA, batch, pooled, N);
    };

    run_branch(xc,  eic, W1c, b1c, g1c, be1c, W2c, b2c, g2c, be2c, pc);
    run_branch(xs_, eis, W1s, b1s, g1s, be1s, W2s, b2s, g2s, be2s, ps);

    // ---- head ----
    k_hcat<<<ceil_div(G * 128, 256), 256>>>(pc, ps, cnt, hcat, G);
    k_gemm<128, 64, 8><<<ceil_div(G, 8), 64>>>(hcat, Wf1, bf1, headT, G);
    k_zero<<<1, 128>>>(stats, 128);
    k_bnstats<<<ceil_div(G, 64), 64>>>(headT, stats, G, 64);
    k_headout<<<ceil_div(G, 256), 256>>>(headT, stats, gf1, bef1, Wf2, bf2,
                                         (float*)d_out, G);
}

// round 2
// speedup vs baseline: 2.0996x; 2.0996x over previous
#include <cuda_runtime.h>

// ---------------- scratch (no allocation allowed) ----------------
#define NMAXN 50048
#define EMAX  600064
#define GMAX  2048

__device__ float g_bufA[NMAXN * 128];
__device__ float g_bufB[NMAXN * 128];
__device__ int   g_deg[NMAXN];
__device__ float g_dinv[NMAXN];
__device__ float g_invdeg[NMAXN];
__device__ int   g_offs[NMAXN + 1];
__device__ int   g_cursor[NMAXN];
__device__ int   g_bsum[512];
__device__ int   g_bsumscan[512];
__device__ int   g_csrc[EMAX];
__device__ float g_cnorm[EMAX];
__device__ float g_stats[512];          // sum[0..M) sumsq[M..2M) scale[2M..3M) shift[3M..4M)
__device__ float g_pc[GMAX * 64];
__device__ float g_ps[GMAX * 64];
__device__ float g_cnt[GMAX];
__device__ float g_hcat[GMAX * 128];
__device__ float g_headT[GMAX * 64];

// ---------------- helpers ----------------
__global__ void k_zero_f(float* p, int n) {
    int i = blockIdx.x * blockDim.x + threadIdx.x;
    if (i < n) p[i] = 0.f;
}
__global__ void k_zero_i(int* p, int n) {
    int i = blockIdx.x * blockDim.x + threadIdx.x;
    if (i < n) p[i] = 0;
}
__global__ void k_count_f(const int* __restrict__ idx, int n, float* __restrict__ acc) {
    int i = blockIdx.x * blockDim.x + threadIdx.x;
    if (i < n) atomicAdd(&acc[idx[i]], 1.f);
}
__global__ void k_count_i(const int* __restrict__ idx, int n, int* __restrict__ acc) {
    int i = blockIdx.x * blockDim.x + threadIdx.x;
    if (i < n) atomicAdd(&acc[idx[i]], 1);
}
__global__ void k_degfin(const int* __restrict__ deg, float* __restrict__ dinv,
                         float* __restrict__ invdeg, int N) {
    int i = blockIdx.x * blockDim.x + threadIdx.x;
    if (i < N) {
        float d = (float)deg[i] + 1.f;
        dinv[i] = rsqrtf(d);
        invdeg[i] = 1.f / d;
    }
}

// ---------------- 3-phase exclusive scan over deg ----------------
__global__ void k_scan1(const int* __restrict__ deg, int* __restrict__ offs,
                        int* __restrict__ bsum, int N) {
    __shared__ int sh[256];
    int tid = threadIdx.x;
    int i = blockIdx.x * 256 + tid;
    int v = (i < N) ? deg[i] : 0;
    sh[tid] = v;
    __syncthreads();
#pragma unroll
    for (int off = 1; off < 256; off <<= 1) {
        int t = (tid >= off) ? sh[tid - off] : 0;
        __syncthreads();
        sh[tid] += t;
        __syncthreads();
    }
    if (i < N) offs[i] = sh[tid] - v;          // exclusive
    if (tid == 255) bsum[blockIdx.x] = sh[255];
}
__global__ void k_scan2(int* __restrict__ bsum, int* __restrict__ bscan, int nb) {
    __shared__ int sh[512];
    int tid = threadIdx.x;
    int v = (tid < nb) ? bsum[tid] : 0;
    sh[tid] = v;
    __syncthreads();
#pragma unroll
    for (int off = 1; off < 512; off <<= 1) {
        int t = (tid >= off) ? sh[tid - off] : 0;
        __syncthreads();
        sh[tid] += t;
        __syncthreads();
    }
    if (tid < nb) bscan[tid] = sh[tid] - v;
}
__global__ void k_scan3(int* __restrict__ offs, int* __restrict__ cursor,
                        const int* __restrict__ bscan, int N, int E) {
    int i = blockIdx.x * blockDim.x + threadIdx.x;
    if (i < N) {
        int o = offs[i] + bscan[blockIdx.x * 256 / 256 == 0 ? blockIdx.x : blockIdx.x];
        o = offs[i] + bscan[i >> 8];
        offs[i] = o;
        cursor[i] = o;
    }
    if (i == 0) offs[N] = E;
}

// build CSR (by dst) with precomputed symmetric norm
__global__ void k_fill(const int* __restrict__ src, const int* __restrict__ dst,
                       const float* __restrict__ dinv, int* __restrict__ cursor,
                       int* __restrict__ csrc, float* __restrict__ cnorm, int E) {
    int e = blockIdx.x * blockDim.x + threadIdx.x;
    if (e >= E) return;
    int s = src[e], d = dst[e];
    int pos = atomicAdd(&cursor[d], 1);
    csrc[pos] = s;
    cnorm[pos] = dinv[s] * dinv[d];
}

// ---------------- GEMM: X[N,K]@W[K,M] (+bias). Optional BN+ReLU on input ----------------
template <int K, int M, int R, bool BN>
__global__ void k_gemm(const float* __restrict__ X, const float* __restrict__ W,
                       const float* __restrict__ bias, const float* __restrict__ stats,
                       float* __restrict__ H, int N) {
    __shared__ float xs[R * K];
    int row0 = blockIdx.x * R;
    for (int i = threadIdx.x; i < R * K; i += M) {
        int r = i / K, k = i - r * K;
        int row = row0 + r;
        float v = (row < N) ? X[(size_t)row * K + k] : 0.f;
        if (BN) v = fmaxf(v * stats[2 * K + k] + stats[3 * K + k], 0.f);
        xs[i] = v;
    }
    __syncthreads();
    int col = threadIdx.x;
    float b = bias ? bias[col] : 0.f;
    float acc[R];
#pragma unroll
    for (int r = 0; r < R; r++) acc[r] = b;
    for (int k = 0; k < K; k++) {
        float w = W[k * M + col];
#pragma unroll
        for (int r = 0; r < R; r++) acc[r] += xs[r * K + k] * w;
    }
#pragma unroll
    for (int r = 0; r < R; r++) {
        int row = row0 + r;
        if (row < N) H[(size_t)row * M + col] = acc[r];
    }
}

// ---------------- gather aggregation: warp per node ----------------
__global__ void k_agg128(const int* __restrict__ offs, const int* __restrict__ csrc,
                         const float* __restrict__ cnorm, const float* __restrict__ H,
                         const float* __restrict__ invdeg, const float* __restrict__ bias,
                         float* __restrict__ out, int N) {
    int node = blockIdx.x * (blockDim.x >> 5) + (threadIdx.x >> 5);
    int lane = threadIdx.x & 31;
    if (node >= N) return;
    float id = invdeg[node];
    float4 acc = *(const float4*)(H + (size_t)node * 128 + lane * 4);
    float4 b = *(const float4*)(bias + lane * 4);
    acc.x = acc.x * id + b.x; acc.y = acc.y * id + b.y;
    acc.z = acc.z * id + b.z; acc.w = acc.w * id + b.w;
    int beg = offs[node], end = offs[node + 1];
    for (int j = beg; j < end; j++) {
        int s = csrc[j];
        float w = cnorm[j];
        float4 h = *(const float4*)(H + (size_t)s * 128 + lane * 4);
        acc.x += h.x * w; acc.y += h.y * w; acc.z += h.z * w; acc.w += h.w * w;
    }
    *(float4*)(out + (size_t)node * 128 + lane * 4) = acc;
}
__global__ void k_agg64(const int* __restrict__ offs, const int* __restrict__ csrc,
                        const float* __restrict__ cnorm, const float* __restrict__ H,
                        const float* __restrict__ invdeg, const float* __restrict__ bias,
                        float* __restrict__ out, int N) {
    int node = blockIdx.x * (blockDim.x >> 5) + (threadIdx.x >> 5);
    int lane = threadIdx.x & 31;
    if (node >= N) return;
    float id = invdeg[node];
    float2 acc = *(const float2*)(H + (size_t)node * 64 + lane * 2);
    float2 b = *(const float2*)(bias + lane * 2);
    acc.x = acc.x * id + b.x; acc.y = acc.y * id + b.y;
    int beg = offs[node], end = offs[node + 1];
    for (int j = beg; j < end; j++) {
        int s = csrc[j];
        float w = cnorm[j];
        float2 h = *(const float2*)(H + (size_t)s * 64 + lane * 2);
        acc.x += h.x * w; acc.y += h.y * w;
    }
    *(float2*)(out + (size_t)node * 64 + lane * 2) = acc;
}

// ---------------- BN ----------------
__global__ void k_bnstats(const float* __restrict__ A, float* __restrict__ stats,
                          int N, int M) {
    int c = threadIdx.x;
    int row0 = blockIdx.x * 64;
    int rend = min(row0 + 64, N);
    float s = 0.f, sq = 0.f;
    for (int r = row0; r < rend; r++) {
        float v = A[(size_t)r * M + c];
        s += v;
        sq += v * v;
    }
    atomicAdd(&stats[c], s);
    atomicAdd(&stats[M + c], sq);
}
// finalize: scale = gamma*rsqrt(var+eps), shift = beta - mean*scale
__global__ void k_bnfin(float* __restrict__ stats, const float* __restrict__ gamma,
                        const float* __restrict__ beta, int M, float inv_n) {
    int c = threadIdx.x;
    if (c >= M) return;
    float mean = stats[c] * inv_n;
    float var = stats[M + c] * inv_n - mean * mean;
    float sc = gamma[c] * rsqrtf(var + 1e-5f);
    stats[2 * M + c] = sc;
    stats[3 * M + c] = beta[c] - mean * sc;
}

// layer-2 BN+ReLU fused with mean-pool accumulation
__global__ void k_bnrelu_pool(const float* __restrict__ A, const float* __restrict__ stats,
                              const int* __restrict__ batch, float* __restrict__ pooled,
                              int N) {
    int idx = blockIdx.x * blockDim.x + threadIdx.x;
    if (idx < N * 64) {
        int i = idx >> 6, c = idx & 63;
        float v = fmaxf(A[idx] * stats[128 + c] + stats[192 + c], 0.f);
        atomicAdd(&pooled[batch[i] * 64 + c], v);
    }
}

__global__ void k_hcat(const float* __restrict__ pc, const float* __restrict__ ps,
                       const float* __restrict__ cnt, float* __restrict__ hcat, int G) {
    int idx = blockIdx.x * blockDim.x + threadIdx.x;
    if (idx < G * 128) {
        int g = idx >> 7, c = idx & 127;
        float inv = 1.f / fmaxf(cnt[g], 1.f);
        hcat[idx] = ((c < 64) ? pc[g * 64 + c] : ps[g * 64 + (c - 64)]) * inv;
    }
}

__global__ void k_headout(const float* __restrict__ T, const float* __restrict__ stats,
                          const float* __restrict__ Wf2, const float* __restrict__ bf2,
                          float* __restrict__ out, int G) {
    int g = blockIdx.x * blockDim.x + threadIdx.x;
    if (g >= G) return;
    float acc = bf2[0];
    for (int j = 0; j < 64; j++) {
        float v = fmaxf(T[g * 64 + j] * stats[128 + j] + stats[192 + j], 0.f);
        acc += v * Wf2[j];
    }
    out[g] = acc;
}

// ---------------- host ----------------
static inline int ceil_div(int a, int b) { return (a + b - 1) / b; }

extern "C" void kernel_launch(void* const* d_in, const int* in_sizes, int n_in,
                              void* d_out, int out_size) {
    const float* xc   = (const float*)d_in[0];
    const float* xs_  = (const float*)d_in[1];
    const int*   eic  = (const int*)d_in[2];
    const int*   eis  = (const int*)d_in[3];
    const int*   batch= (const int*)d_in[4];
    const float* W1c = (const float*)d_in[5],  *b1c = (const float*)d_in[6];
    const float* g1c = (const float*)d_in[7],  *be1c= (const float*)d_in[8];
    const float* W2c = (const float*)d_in[9],  *b2c = (const float*)d_in[10];
    const float* g2c = (const float*)d_in[11], *be2c= (const float*)d_in[12];
    const float* W1s = (const float*)d_in[13], *b1s = (const float*)d_in[14];
    const float* g1s = (const float*)d_in[15], *be1s= (const float*)d_in[16];
    const float* W2s = (const float*)d_in[17], *b2s = (const float*)d_in[18];
    const float* g2s = (const float*)d_in[19], *be2s= (const float*)d_in[20];
    const float* Wf1 = (const float*)d_in[21], *bf1 = (const float*)d_in[22];
    const float* gf1 = (const float*)d_in[23], *bef1= (const float*)d_in[24];
    const float* Wf2 = (const float*)d_in[25], *bf2 = (const float*)d_in[26];

    const int N = in_sizes[0] / 64;
    const int E = in_sizes[2] / 2;
    const int G = out_size;

    float *bufA, *bufB, *dinv, *invdeg, *stats, *pc, *ps, *cnt, *hcat, *headT, *cnorm;
    int *deg, *offs, *cursor, *bsum, *bscan, *csrc;
    cudaGetSymbolAddress((void**)&bufA, g_bufA);
    cudaGetSymbolAddress((void**)&bufB, g_bufB);
    cudaGetSymbolAddress((void**)&deg, g_deg);
    cudaGetSymbolAddress((void**)&dinv, g_dinv);
    cudaGetSymbolAddress((void**)&invdeg, g_invdeg);
    cudaGetSymbolAddress((void**)&offs, g_offs);
    cudaGetSymbolAddress((void**)&cursor, g_cursor);
    cudaGetSymbolAddress((void**)&bsum, g_bsum);
    cudaGetSymbolAddress((void**)&bscan, g_bsumscan);
    cudaGetSymbolAddress((void**)&csrc, g_csrc);
    cudaGetSymbolAddress((void**)&cnorm, g_cnorm);
    cudaGetSymbolAddress((void**)&stats, g_stats);
    cudaGetSymbolAddress((void**)&pc, g_pc);
    cudaGetSymbolAddress((void**)&ps, g_ps);
    cudaGetSymbolAddress((void**)&cnt, g_cnt);
    cudaGetSymbolAddress((void**)&hcat, g_hcat);
    cudaGetSymbolAddress((void**)&headT, g_headT);

    const int nb = ceil_div(N, 256);

    k_zero_f<<<ceil_div(G * 64, 256), 256>>>(pc, G * 64);
    k_zero_f<<<ceil_div(G * 64, 256), 256>>>(ps, G * 64);
    k_zero_f<<<ceil_div(G, 256), 256>>>(cnt, G);
    k_count_f<<<ceil_div(N, 256), 256>>>(batch, N, cnt);

    auto run_branch = [&](const float* x, const int* ei,
                          const float* W1, const float* b1, const float* ga1, const float* bt1,
                          const float* W2, const float* b2, const float* ga2, const float* bt2,
                          float* pooled) {
        const int* src = ei;
        const int* dst = ei + E;

        // ---- CSR build (by dst) ----
        k_zero_i<<<nb, 256>>>(deg, N);
        k_count_i<<<ceil_div(E, 256), 256>>>(dst, E, deg);
        k_degfin<<<nb, 256>>>(deg, dinv, invdeg, N);
        k_scan1<<<nb, 256>>>(deg, offs, bsum, N);
        k_scan2<<<1, 512>>>(bsum, bscan, nb);
        k_scan3<<<nb, 256>>>(offs, cursor, bscan, N, E);
        k_fill<<<ceil_div(E, 256), 256>>>(src, dst, dinv, cursor, csrc, cnorm, E);

        // ---- layer 1: 64 -> 128 ----
        k_gemm<64, 128, 8, false><<<ceil_div(N, 8), 128>>>(x, W1, nullptr, nullptr, bufB, N);
        k_agg128<<<ceil_div(N, 8), 256>>>(offs, csrc, cnorm, bufB, invdeg, b1, bufA, N);
        k_zero_f<<<1, 512>>>(stats, 512);
        k_bnstats<<<ceil_div(N, 64), 128>>>(bufA, stats, N, 128);
        k_bnfin<<<1, 128>>>(stats, ga1, bt1, 128, 1.f / (float)N);

        // ---- layer 2: 128 -> 64 (BN+ReLU fused into GEMM input) ----
        k_gemm<128, 64, 8, true><<<ceil_div(N, 8), 64>>>(bufA, W2, nullptr, stats, bufB, N);
        k_agg64<<<ceil_div(N, 8), 256>>>(offs, csrc, cnorm, bufB, invdeg, b2, bufA, N);
        k_zero_f<<<1, 512>>>(stats, 512);
        k_bnstats<<<ceil_div(N, 64), 64>>>(bufA, stats, N, 64);
        k_bnfin<<<1, 64>>>(stats, ga2, bt2, 64, 1.f / (float)N);

        // ---- BN+ReLU + mean pool (sum; divided in hcat) ----
        k_bnrelu_pool<<<ceil_div(N * 64, 256), 256>>>(bufA, stats, batch, pooled, N);
    };

    run_branch(xc,  eic, W1c, b1c, g1c, be1c, W2c, b2c, g2c, be2c, pc);
    run_branch(xs_, eis, W1s, b1s, g1s, be1s, W2s, b2s, g2s, be2s, ps);

    // ---- head ----
    k_hcat<<<ceil_div(G * 128, 256), 256>>>(pc, ps, cnt, hcat, G);
    k_gemm<128, 64, 8, false><<<ceil_div(G, 8), 64>>>(hcat, Wf1, bf1, nullptr, headT, G);
    k_zero_f<<<1, 512>>>(stats, 512);
    k_bnstats<<<ceil_div(G, 64), 64>>>(headT, stats, G, 64);
    k_bnfin<<<1, 64>>>(stats, gf1, bef1, 64, 1.f / (float)G);
    k_headout<<<ceil_div(G, 256), 256>>>(headT, stats, Wf2, bf2, (float*)d_out, G);
}